// round 16
// baseline (speedup 1.0000x reference)
#include <cuda_runtime.h>
#include <cuda_bf16.h>
#include <cstdint>

#define NMAX 50000
#define EMAX 800000
#define DIM  128
#define ODIM 64
#define STRIDE 68   // A-buffer words per 128-col row
#define WSTR   36   // W-chunk buffer words per row (64-k chunk)
#define SCANB  4096
#define MAXSB  64
#define WSPLIT 49152  // 3*2*2*4096 weight-split words
#define WLINW  4096   // Wlin split words
#define TM     64     // MLP tile rows

// ---------------- scratch (device globals; no allocations) ----------------
__device__ float    g_h[NMAX * DIM];
__device__ unsigned g_ah[NMAX * 64];
__device__ unsigned g_al[NMAX * 64];
__device__ unsigned g_wsph[WSPLIT];
__device__ unsigned g_wspl[WSPLIT];
__device__ unsigned g_wlh[WLINW];
__device__ unsigned g_wll[WLINW];
__device__ unsigned g_mask[NMAX * 4];
__device__ int      g_rowptr[NMAX + 1];
__device__ int      g_cursor[NMAX];
__device__ int      g_srcs[EMAX];
__device__ unsigned long long g_bpack[MAXSB];

// ---------------- threefry2x32 (exact JAX, partitionable mode) -------------
__host__ __device__ __forceinline__ unsigned rotl32(unsigned x, int r) {
    return (x << r) | (x >> (32 - r));
}

__host__ __device__ __forceinline__ void threefry2x32(
    unsigned k0, unsigned k1, unsigned x0, unsigned x1,
    unsigned& o0, unsigned& o1)
{
    unsigned ks0 = k0, ks1 = k1, ks2 = k0 ^ k1 ^ 0x1BD11BDAu;
    x0 += ks0; x1 += ks1;
#define TFR(r) { x0 += x1; x1 = rotl32(x1, r); x1 ^= x0; }
    TFR(13) TFR(15) TFR(26) TFR(6)   x0 += ks1; x1 += ks2 + 1u;
    TFR(17) TFR(29) TFR(16) TFR(24)  x0 += ks2; x1 += ks0 + 2u;
    TFR(13) TFR(15) TFR(26) TFR(6)   x0 += ks0; x1 += ks1 + 3u;
    TFR(17) TFR(29) TFR(16) TFR(24)  x0 += ks1; x1 += ks2 + 4u;
    TFR(13) TFR(15) TFR(26) TFR(6)   x0 += ks2; x1 += ks0 + 5u;
#undef TFR
    o0 = x0; o1 = x1;
}

// ---------------- bf16 split helpers ----------------------------------------
__device__ __forceinline__ void bsplit(float x, __nv_bfloat16& h, __nv_bfloat16& l) {
    h = __float2bfloat16(x);
    l = __float2bfloat16(x - __bfloat162float(h));
}

__device__ __forceinline__ unsigned packbf(__nv_bfloat16 lo16, __nv_bfloat16 hi16) {
    unsigned a = *(unsigned short*)&lo16;
    unsigned b = *(unsigned short*)&hi16;
    return a | (b << 16);
}

__device__ __forceinline__ uint32_t smem_u32(const void* p) {
    uint32_t a;
    asm("{ .reg .u64 t; cvta.to.shared.u64 t, %1; cvt.u32.u64 %0, t; }"
        : "=r"(a) : "l"(p));
    return a;
}

// ---------------- cp.async helpers -------------------------------------------
#define CP_ASYNC16(saddr, gptr) \
    asm volatile("cp.async.cg.shared.global [%0], [%1], 16;" \
                 :: "r"(saddr), "l"(gptr) : "memory")
#define CP_COMMIT() asm volatile("cp.async.commit_group;" ::: "memory")
#define CP_WAIT0()  asm volatile("cp.async.wait_group 0;" ::: "memory")

// ---------------- mma.sync bf16 m16n8k16 ------------------------------------
#define MMA_BF16(d, a0, a1, a2, a3, b0, b1)                                   \
    asm volatile("mma.sync.aligned.m16n8k16.row.col.f32.bf16.bf16.f32 "       \
        "{%0,%1,%2,%3}, {%4,%5,%6,%7}, {%8,%9}, {%0,%1,%2,%3};"               \
        : "+f"((d)[0]), "+f"((d)[1]), "+f"((d)[2]), "+f"((d)[3])              \
        : "r"(a0), "r"(a1), "r"(a2), "r"(a3), "r"(b0), "r"(b1))

// GEMM with fragment reuse; A tile rows addressed wr*32 + mt*16 (+8).
template<int NT, int BSTR, int NKS>
__device__ __forceinline__ void gemm_frag(
    const unsigned* __restrict__ Ah, const unsigned* __restrict__ Al,
    const unsigned* __restrict__ Bh, const unsigned* __restrict__ Bl,
    float acc[2][NT][4], int wr, int wn, int g, int t, int akw0)
{
#pragma unroll 1
    for (int ks = 0; ks < NKS; ks++) {
        const int kw = ks * 8;
        unsigned ah[2][4], al[2][4];
#pragma unroll
        for (int mt = 0; mt < 2; mt++) {
            const int r0 = (wr * 32 + mt * 16 + g) * STRIDE + akw0 + kw + t;
            const int r1 = r0 + 8 * STRIDE;
            ah[mt][0] = Ah[r0];     ah[mt][1] = Ah[r1];
            ah[mt][2] = Ah[r0 + 4]; ah[mt][3] = Ah[r1 + 4];
            al[mt][0] = Al[r0];     al[mt][1] = Al[r1];
            al[mt][2] = Al[r0 + 4]; al[mt][3] = Al[r1 + 4];
        }
#pragma unroll
        for (int nt = 0; nt < NT; nt++) {
            const int nb = (wn * (NT * 8) + nt * 8 + g) * BSTR + kw + t;
            const unsigned bh0 = Bh[nb], bh1 = Bh[nb + 4];
            const unsigned bl0 = Bl[nb], bl1 = Bl[nb + 4];
            MMA_BF16(acc[0][nt], ah[0][0], ah[0][1], ah[0][2], ah[0][3], bh0, bh1);
            MMA_BF16(acc[1][nt], ah[1][0], ah[1][1], ah[1][2], ah[1][3], bh0, bh1);
            MMA_BF16(acc[0][nt], ah[0][0], ah[0][1], ah[0][2], ah[0][3], bl0, bl1);
            MMA_BF16(acc[1][nt], ah[1][0], ah[1][1], ah[1][2], ah[1][3], bl0, bl1);
            MMA_BF16(acc[0][nt], al[0][0], al[0][1], al[0][2], al[0][3], bh0, bh1);
            MMA_BF16(acc[1][nt], al[1][0], al[1][1], al[1][2], al[1][3], bh0, bh1);
        }
    }
}

// ---------------- prep: W splits + flag reset + cursor zero ------------------
__global__ __launch_bounds__(256) void k_prep(
    const float* __restrict__ Ws1, const float* __restrict__ Ws2,
    const float* __restrict__ Wlin, int n)
{
    int idx = blockIdx.x * blockDim.x + threadIdx.x;
    if (idx < WSPLIT) {
        int w  = idx & 31;
        int nn = (idx >> 5) & 127;
        int c  = (idx >> 12) & 1;
        int m  = (idx >> 13) & 1;
        int l  = idx >> 14;
        const float* W = (m == 0 ? Ws1 : Ws2) + (size_t)l * DIM * DIM;
        int k0 = c * 64 + 2 * w;
        float w0 = W[(size_t)k0 * DIM + nn];
        float w1 = W[(size_t)(k0 + 1) * DIM + nn];
        __nv_bfloat16 h0, l0, h1, l1;
        bsplit(w0, h0, l0); bsplit(w1, h1, l1);
        g_wsph[idx] = packbf(h0, h1);
        g_wspl[idx] = packbf(l0, l1);
    } else if (idx < WSPLIT + WLINW) {
        int i = idx - WSPLIT;
        int nn = i >> 6;
        int w  = i & 63;
        int k0 = 2 * w;
        float w0 = Wlin[(size_t)k0 * ODIM + nn];
        float w1 = Wlin[(size_t)(k0 + 1) * ODIM + nn];
        __nv_bfloat16 h0, l0, h1, l1;
        bsplit(w0, h0, l0); bsplit(w1, h1, l1);
        g_wlh[nn * 64 + w] = packbf(h0, h1);
        g_wll[nn * 64 + w] = packbf(l0, l1);
    } else if (idx < WSPLIT + WLINW + MAXSB) {
        g_bpack[idx - WSPLIT - WLINW] = 0ULL;
    } else {
        int i = idx - WSPLIT - WLINW - MAXSB;
        if (i < n) g_cursor[i] = 0;
    }
}

// ---------------- CSR build (4 edges/thread via int4) ------------------------
__global__ __launch_bounds__(256) void k_hist(const int* __restrict__ ei, int e, int n) {
    int i4 = (blockIdx.x * blockDim.x + threadIdx.x) * 4;
    if (i4 >= e) return;
    if ((e & 3) == 0) {
        int4 d = *(const int4*)(ei + e + i4);
        if ((unsigned)d.x < (unsigned)n) atomicAdd(&g_cursor[d.x], 1);
        if ((unsigned)d.y < (unsigned)n) atomicAdd(&g_cursor[d.y], 1);
        if ((unsigned)d.z < (unsigned)n) atomicAdd(&g_cursor[d.z], 1);
        if ((unsigned)d.w < (unsigned)n) atomicAdd(&g_cursor[d.w], 1);
    } else {
        for (int q = 0; q < 4 && i4 + q < e; q++) {
            int dst = ei[e + i4 + q];
            if ((unsigned)dst < (unsigned)n) atomicAdd(&g_cursor[dst], 1);
        }
    }
}

// fused scan: per-block scan + decoupled lookback + rowptr/cursor writes
__global__ __launch_bounds__(1024) void k_scan(int n, int nblk) {
    __shared__ int wsum[32];
    __shared__ int soff;
    const int t = threadIdx.x, lane = t & 31, w = t >> 5;
    const int base = blockIdx.x * SCANB + t * 4;
    int v0 = 0, v1 = 0, v2 = 0, v3 = 0;
    if (base + 0 < n) v0 = g_cursor[base + 0];
    if (base + 1 < n) v1 = g_cursor[base + 1];
    if (base + 2 < n) v2 = g_cursor[base + 2];
    if (base + 3 < n) v3 = g_cursor[base + 3];
    int s = v0 + v1 + v2 + v3;
    int x = s;
#pragma unroll
    for (int off = 1; off < 32; off <<= 1) {
        int y = __shfl_up_sync(0xffffffffu, x, off);
        if (lane >= off) x += y;
    }
    if (lane == 31) wsum[w] = x;
    __syncthreads();
    if (w == 0) {
        int y = wsum[lane];
#pragma unroll
        for (int off = 1; off < 32; off <<= 1) {
            int z2 = __shfl_up_sync(0xffffffffu, y, off);
            if (lane >= off) y += z2;
        }
        wsum[lane] = y;
    }
    __syncthreads();
    const int total = wsum[31];
    if (t == 0) {
        atomicExch(&g_bpack[blockIdx.x],
                   (1ULL << 63) | (unsigned long long)(unsigned)total);
        int run = 0;
        for (int b = 0; b < blockIdx.x; b++) {
            unsigned long long v;
            do { v = atomicAdd(&g_bpack[b], 0ULL); } while (!(v >> 63));
            run += (int)(unsigned)(v & 0xffffffffULL);
        }
        soff = run;
        if (blockIdx.x == nblk - 1) g_rowptr[n] = run + total;
    }
    __syncthreads();
    const int excl = (x - s) + (w ? wsum[w - 1] : 0) + soff;
    if (base + 0 < n) { int v = excl;                 g_rowptr[base + 0] = v; g_cursor[base + 0] = v; }
    if (base + 1 < n) { int v = excl + v0;            g_rowptr[base + 1] = v; g_cursor[base + 1] = v; }
    if (base + 2 < n) { int v = excl + v0 + v1;       g_rowptr[base + 2] = v; g_cursor[base + 2] = v; }
    if (base + 3 < n) { int v = excl + v0 + v1 + v2;  g_rowptr[base + 3] = v; g_cursor[base + 3] = v; }
}

__global__ __launch_bounds__(256) void k_scatter(const int* __restrict__ ei, int e, int n) {
    int i4 = (blockIdx.x * blockDim.x + threadIdx.x) * 4;
    if (i4 >= e) return;
    if ((e & 3) == 0) {
        int4 s = *(const int4*)(ei + i4);
        int4 d = *(const int4*)(ei + e + i4);
        if ((unsigned)d.x < (unsigned)n && (unsigned)s.x < (unsigned)n) {
            int pos = atomicAdd(&g_cursor[d.x], 1);
            if ((unsigned)pos < (unsigned)EMAX) g_srcs[pos] = s.x;
        }
        if ((unsigned)d.y < (unsigned)n && (unsigned)s.y < (unsigned)n) {
            int pos = atomicAdd(&g_cursor[d.y], 1);
            if ((unsigned)pos < (unsigned)EMAX) g_srcs[pos] = s.y;
        }
        if ((unsigned)d.z < (unsigned)n && (unsigned)s.z < (unsigned)n) {
            int pos = atomicAdd(&g_cursor[d.z], 1);
            if ((unsigned)pos < (unsigned)EMAX) g_srcs[pos] = s.z;
        }
        if ((unsigned)d.w < (unsigned)n && (unsigned)s.w < (unsigned)n) {
            int pos = atomicAdd(&g_cursor[d.w], 1);
            if ((unsigned)pos < (unsigned)EMAX) g_srcs[pos] = s.w;
        }
    } else {
        for (int q = 0; q < 4 && i4 + q < e; q++) {
            int dst = ei[e + i4 + q];
            int src = ei[i4 + q];
            if ((unsigned)dst < (unsigned)n && (unsigned)src < (unsigned)n) {
                int pos = atomicAdd(&g_cursor[dst], 1);
                if ((unsigned)pos < (unsigned)EMAX) g_srcs[pos] = src;
            }
        }
    }
}

// ---------- aggregation + split + dropout mask gen (warp per node) ----------
__global__ __launch_bounds__(256) void k_aggregate(
    const float* __restrict__ xin, int use_x, int n,
    unsigned dk0, unsigned dk1)
{
    const int gw = (blockIdx.x * 256 + threadIdx.x) >> 5;
    if (gw >= n) return;
    const int lane = threadIdx.x & 31;

    const unsigned base_j = (unsigned)gw * 128u + (unsigned)lane;
#pragma unroll
    for (int w = 0; w < 4; w++) {
        unsigned a, b;
        threefry2x32(dk0, dk1, 0u, base_j + (unsigned)(w * 32), a, b);
        unsigned bits = a ^ b;
        float u = __uint_as_float((bits >> 9) | 0x3f800000u) - 1.0f;
        unsigned word = __ballot_sync(0xffffffffu, u < 0.9f);
        if (lane == w) g_mask[gw * 4 + w] = word;
    }

    const float4* b4 = (const float4*)(use_x ? xin : g_h);
    float4 acc = b4[(size_t)gw * 32 + lane];
    int p = g_rowptr[gw];
    const int pe = g_rowptr[gw + 1];
    for (; p + 4 <= pe; p += 4) {
        int s0 = g_srcs[p], s1 = g_srcs[p + 1], s2 = g_srcs[p + 2], s3 = g_srcs[p + 3];
        float4 v0 = b4[(size_t)s0 * 32 + lane];
        float4 v1 = b4[(size_t)s1 * 32 + lane];
        float4 v2 = b4[(size_t)s2 * 32 + lane];
        float4 v3 = b4[(size_t)s3 * 32 + lane];
        acc.x += v0.x; acc.y += v0.y; acc.z += v0.z; acc.w += v0.w;
        acc.x += v1.x; acc.y += v1.y; acc.z += v1.z; acc.w += v1.w;
        acc.x += v2.x; acc.y += v2.y; acc.z += v2.z; acc.w += v2.w;
        acc.x += v3.x; acc.y += v3.y; acc.z += v3.z; acc.w += v3.w;
    }
    for (; p < pe; ++p) {
        float4 v = b4[(size_t)g_srcs[p] * 32 + lane];
        acc.x += v.x; acc.y += v.y; acc.z += v.z; acc.w += v.w;
    }
    __nv_bfloat16 h0, l0, h1, l1, h2, l2, h3, l3;
    bsplit(acc.x, h0, l0); bsplit(acc.y, h1, l1);
    bsplit(acc.z, h2, l2); bsplit(acc.w, h3, l3);
    const size_t o = (size_t)gw * 64 + lane * 2;
    g_ah[o]     = packbf(h0, h1);
    g_ah[o + 1] = packbf(h2, h3);
    g_al[o]     = packbf(l0, l1);
    g_al[o + 1] = packbf(l2, l3);
}

// ------------ fused MLP, 64-row tiles, cp.async double-buffered W ------------
#define BUFW     (TM * STRIDE)                 // 4352 words
#define WBUF     (128 * WSTR)                  // 4608 words
#define SMEM_MMA (2048 + 2 * BUFW * 4 + 4 * WBUF * 4)   // 110,592 B

template<bool DO_LIN>
__global__ __launch_bounds__(256, 2) void k_mlp_mma(
    const float* __restrict__ b1g, const float* __restrict__ b2g,
    const float* __restrict__ blin, float* __restrict__ outp,
    int lidx, int nrows)
{
    extern __shared__ char smem[];
    float*    sB1 = (float*)smem;
    float*    sB2 = (float*)(smem + 512);
    float*    sBo = (float*)(smem + 1024);
    unsigned* sAh = (unsigned*)(smem + 2048);
    unsigned* sAl = sAh + BUFW;
    unsigned* sW0h = sAl + BUFW;
    unsigned* sW0l = sW0h + WBUF;
    unsigned* sW1h = sW0l + WBUF;
    unsigned* sW1l = sW1h + WBUF;

    const uint32_t uW0h = smem_u32(sW0h), uW0l = smem_u32(sW0l);
    const uint32_t uW1h = smem_u32(sW1h), uW1l = smem_u32(sW1l);

    const int tid = threadIdx.x;
    const int wid = tid >> 5;
    const int lane = tid & 31;
    const int wr = wid & 1;
    const int wn = wid >> 1;
    const int g = lane >> 2;
    const int t = lane & 3;

    const int row0 = blockIdx.x * TM;
    const int avail = (nrows - row0 < TM) ? (nrows - row0) : TM;

    // W-chunk sources for this layer (m=0 -> W1, m=1 -> W2)
    const unsigned* gw_h[4];
    const unsigned* gw_l[4];
#pragma unroll
    for (int q = 0; q < 4; q++) {
        int m = q >> 1, c = q & 1;
        gw_h[q] = g_wsph + ((lidx * 2 + m) * 2 + c) * 4096;
        gw_l[q] = g_wspl + ((lidx * 2 + m) * 2 + c) * 4096;
    }

    // async-stage one W chunk into buffer (uh, ul)
    auto stage_w = [&](uint32_t uh, uint32_t ul, const unsigned* gh, const unsigned* gl) {
#pragma unroll
        for (int i = tid; i < 1024; i += 256) {
            int nn = i >> 3;
            int w4 = (i & 7) * 4;
            uint32_t off = (uint32_t)(nn * WSTR + w4) * 4u;
            CP_ASYNC16(uh + off, gh + nn * 32 + w4);
            CP_ASYNC16(ul + off, gl + nn * 32 + w4);
        }
        CP_COMMIT();
    };

    if (tid < 128) { sB1[tid] = b1g[tid]; sB2[tid] = b2g[tid]; }
    if (DO_LIN && tid < 64) sBo[tid] = blin[tid];

    stage_w(uW0h, uW0l, gw_h[0], gw_l[0]);          // W1c0 -> buf0 (async)

    // stage A tile (plain, overlaps with W1c0 in flight)
    for (int i = tid; i < 1024; i += 256) {
        int r  = i >> 4;
        int w4 = (i & 15) * 4;
        uint4 vh = make_uint4(0, 0, 0, 0), vl = make_uint4(0, 0, 0, 0);
        if (r < avail) {
            vh = *(const uint4*)(g_ah + (size_t)(row0 + r) * 64 + w4);
            vl = *(const uint4*)(g_al + (size_t)(row0 + r) * 64 + w4);
        }
        *(uint4*)(sAh + r * STRIDE + w4) = vh;
        *(uint4*)(sAl + r * STRIDE + w4) = vl;
    }

    float acc[2][4][4];
#pragma unroll
    for (int mt = 0; mt < 2; mt++)
#pragma unroll
        for (int nt = 0; nt < 4; nt++)
#pragma unroll
            for (int q = 0; q < 4; q++) acc[mt][nt][q] = 0.f;

    CP_WAIT0(); __syncthreads();                     // buf0 + A ready

    stage_w(uW1h, uW1l, gw_h[1], gw_l[1]);           // W1c1 -> buf1 (async)
    gemm_frag<4, WSTR, 4>(sAh, sAl, sW0h, sW0l, acc, wr, wn, g, t, 0);
    CP_WAIT0(); __syncthreads();                     // buf1 ready; buf0 free

    stage_w(uW0h, uW0l, gw_h[2], gw_l[2]);           // W2c0 -> buf0 (async)
    gemm_frag<4, WSTR, 4>(sAh, sAl, sW1h, sW1l, acc, wr, wn, g, t, 32);
    __syncthreads();                                 // all sA reads done

    // epilogue1: t = relu(D1 + b1) -> split back into sAh/sAl
#pragma unroll
    for (int mt = 0; mt < 2; mt++) {
        const int r0 = wr * 32 + mt * 16 + g;
#pragma unroll
        for (int nt = 0; nt < 4; nt++) {
            const int c0 = wn * 32 + nt * 8 + 2 * t;
            const float bv0 = sB1[c0], bv1 = sB1[c0 + 1];
            float v00 = fmaxf(acc[mt][nt][0] + bv0, 0.f);
            float v01 = fmaxf(acc[mt][nt][1] + bv1, 0.f);
            float v10 = fmaxf(acc[mt][nt][2] + bv0, 0.f);
            float v11 = fmaxf(acc[mt][nt][3] + bv1, 0.f);
            __nv_bfloat16 h00, l00, h01, l01, h10, l10, h11, l11;
            bsplit(v00, h00, l00); bsplit(v01, h01, l01);
            bsplit(v10, h10, l10); bsplit(v11, h11, l11);
            const int w0 = r0 * STRIDE + (c0 >> 1);
            const int w1 = w0 + 8 * STRIDE;
            sAh[w0] = packbf(h00, h01);  sAl[w0] = packbf(l00, l01);
            sAh[w1] = packbf(h10, h11);  sAl[w1] = packbf(l10, l11);
            acc[mt][nt][0] = 0.f; acc[mt][nt][1] = 0.f;
            acc[mt][nt][2] = 0.f; acc[mt][nt][3] = 0.f;
        }
    }
    CP_WAIT0(); __syncthreads();                     // buf0(W2c0) + sA(t) ready

    stage_w(uW1h, uW1l, gw_h[3], gw_l[3]);           // W2c1 -> buf1 (async)
    gemm_frag<4, WSTR, 4>(sAh, sAl, sW0h, sW0l, acc, wr, wn, g, t, 0);
    CP_WAIT0(); __syncthreads();                     // buf1 ready

    gemm_frag<4, WSTR, 4>(sAh, sAl, sW1h, sW1l, acc, wr, wn, g, t, 32);

    // precomputed dropout mask (one word per (row, wn))
    unsigned mw[2][2];
#pragma unroll
    for (int mt = 0; mt < 2; mt++)
#pragma unroll
        for (int rr = 0; rr < 2; rr++) {
            int grow = row0 + wr * 32 + mt * 16 + g + rr * 8;
            mw[mt][rr] = (grow < nrows) ? g_mask[grow * 4 + wn] : 0u;
        }
    const float INV = 1.0f / 0.9f;

    if (DO_LIN) __syncthreads();                     // before epilogue2 writes sA

    // epilogue2: h = dropout(relu(D2 + b2))
#pragma unroll
    for (int mt = 0; mt < 2; mt++) {
        const int r0 = wr * 32 + mt * 16 + g;
        const int grow0 = row0 + r0;
        const int grow1 = grow0 + 8;
#pragma unroll
        for (int nt = 0; nt < 4; nt++) {
            const int c0 = wn * 32 + nt * 8 + 2 * t;
            const float bv0 = sB2[c0], bv1 = sB2[c0 + 1];
            const int b0 = nt * 8 + 2 * t;
            {
                float m0 = ((mw[mt][0] >> b0) & 1u) ? INV : 0.f;
                float m1 = ((mw[mt][0] >> (b0 + 1)) & 1u) ? INV : 0.f;
                float v0 = fmaxf(acc[mt][nt][0] + bv0, 0.f) * m0;
                float v1 = fmaxf(acc[mt][nt][1] + bv1, 0.f) * m1;
                if (DO_LIN) {
                    __nv_bfloat16 h0, l0, h1, l1;
                    bsplit(v0, h0, l0); bsplit(v1, h1, l1);
                    const int w0 = r0 * STRIDE + (c0 >> 1);
                    sAh[w0] = packbf(h0, h1);  sAl[w0] = packbf(l0, l1);
                } else if (grow0 < nrows) {
                    *(float2*)(g_h + (size_t)grow0 * DIM + c0) = make_float2(v0, v1);
                }
            }
            {
                float m0 = ((mw[mt][1] >> b0) & 1u) ? INV : 0.f;
                float m1 = ((mw[mt][1] >> (b0 + 1)) & 1u) ? INV : 0.f;
                float v0 = fmaxf(acc[mt][nt][2] + bv0, 0.f) * m0;
                float v1 = fmaxf(acc[mt][nt][3] + bv1, 0.f) * m1;
                if (DO_LIN) {
                    __nv_bfloat16 h0, l0, h1, l1;
                    bsplit(v0, h0, l0); bsplit(v1, h1, l1);
                    const int w1 = (r0 + 8) * STRIDE + (c0 >> 1);
                    sAh[w1] = packbf(h0, h1);  sAl[w1] = packbf(l0, l1);
                } else if (grow1 < nrows) {
                    *(float2*)(g_h + (size_t)grow1 * DIM + c0) = make_float2(v0, v1);
                }
            }
        }
    }

    if (DO_LIN) {
        __syncthreads();
        // stage Wlin split: 64 rows x 64 words (stride STRIDE; 4352 <= WBUF)
        for (int i = tid; i < 1024; i += 256) {
            int nn = i >> 4;
            int w4 = (i & 15) * 4;
            *(uint4*)(sW0h + nn * STRIDE + w4) = *(const uint4*)(g_wlh + nn * 64 + w4);
            *(uint4*)(sW0l + nn * STRIDE + w4) = *(const uint4*)(g_wll + nn * 64 + w4);
        }
        __syncthreads();

        float la[2][2][4];
#pragma unroll
        for (int mt = 0; mt < 2; mt++)
#pragma unroll
            for (int nt = 0; nt < 2; nt++)
#pragma unroll
                for (int q = 0; q < 4; q++) la[mt][nt][q] = 0.f;

        gemm_frag<2, STRIDE, 8>(sAh, sAl, sW0h, sW0l, la, wr, wn, g, t, 0);

#pragma unroll
        for (int mt = 0; mt < 2; mt++) {
            const int grow0 = row0 + wr * 32 + mt * 16 + g;
            const int grow1 = grow0 + 8;
#pragma unroll
            for (int nt = 0; nt < 2; nt++) {
                const int c0 = wn * 16 + nt * 8 + 2 * t;
                const float bv0 = sBo[c0], bv1 = sBo[c0 + 1];
                if (grow0 < nrows)
                    *(float2*)(outp + (size_t)grow0 * ODIM + c0) =
                        make_float2(la[mt][nt][0] + bv0, la[mt][nt][1] + bv1);
                if (grow1 < nrows)
                    *(float2*)(outp + (size_t)grow1 * ODIM + c0) =
                        make_float2(la[mt][nt][2] + bv0, la[mt][nt][3] + bv1);
            }
        }
    }
}

// ---------------- launch ----------------------------------------------------
extern "C" void kernel_launch(void* const* d_in, const int* in_sizes, int n_in,
                              void* d_out, int out_size)
{
    const float* x    = (const float*)d_in[0];
    const int*   ei   = (const int*)d_in[1];
    const float* Ws1  = (const float*)d_in[2];
    const float* bs1  = (const float*)d_in[3];
    const float* Ws2  = (const float*)d_in[4];
    const float* bs2  = (const float*)d_in[5];
    const float* Wlin = (const float*)d_in[6];
    const float* blin = (const float*)d_in[7];
    float*       out  = (float*)d_out;

    const int n = in_sizes[0] / DIM;
    const int e = in_sizes[1] / 2;
    if (n > NMAX || e > EMAX || n <= 0) return;

    cudaFuncSetAttribute(k_mlp_mma<false>, cudaFuncAttributeMaxDynamicSharedMemorySize, SMEM_MMA);
    cudaFuncSetAttribute(k_mlp_mma<true>,  cudaFuncAttributeMaxDynamicSharedMemorySize, SMEM_MMA);

    unsigned dk0[3], dk1[3];
    for (int l = 0; l < 3; l++)
        threefry2x32(0u, 42u, 0u, (unsigned)l, dk0[l], dk1[l]);

    const int nsb = (n + SCANB - 1) / SCANB;
    const int e4  = (e + 3) / 4;

    k_prep   <<<(WSPLIT + WLINW + MAXSB + n + 255) / 256, 256>>>(Ws1, Ws2, Wlin, n);
    k_hist   <<<(e4 + 255) / 256, 256>>>(ei, e, n);
    k_scan   <<<nsb, 1024>>>(n, nsb);
    k_scatter<<<(e4 + 255) / 256, 256>>>(ei, e, n);

    const int gblk = (n + TM - 1) / TM;
    const int ablk = (n * 32 + 255) / 256;
    for (int l = 0; l < 3; l++) {
        k_aggregate<<<ablk, 256>>>(x, l == 0 ? 1 : 0, n, dk0[l], dk1[l]);
        if (l < 2)
            k_mlp_mma<false><<<gblk, 256, SMEM_MMA>>>(
                bs1 + (size_t)l * DIM, bs2 + (size_t)l * DIM,
                blin, out, l, n);
        else
            k_mlp_mma<true><<<gblk, 256, SMEM_MMA>>>(
                bs1 + (size_t)l * DIM, bs2 + (size_t)l * DIM,
                blin, out, l, n);
    }
}

// round 17
// speedup vs baseline: 1.0137x; 1.0137x over previous
#include <cuda_runtime.h>
#include <cuda_bf16.h>
#include <cstdint>

#define NMAX 50000
#define EMAX 800000
#define DIM  128
#define ODIM 64
#define STRIDE 68   // A-buffer words per 128-col row
#define WSTR   36   // W-chunk buffer words per row (64-k chunk)
#define SCANB  4096
#define MAXSB  64
#define WSPLIT 49152  // 3*2*2*4096 weight-split words
#define WLINW  4096   // Wlin split words
#define TM     64     // MLP tile rows

// ---------------- scratch (device globals; no allocations) ----------------
__device__ float    g_h[NMAX * DIM];
__device__ unsigned g_ah[NMAX * 64];
__device__ unsigned g_al[NMAX * 64];
__device__ unsigned g_wsph[WSPLIT];
__device__ unsigned g_wspl[WSPLIT];
__device__ unsigned g_wlh[WLINW];
__device__ unsigned g_wll[WLINW];
__device__ unsigned g_mask[NMAX * 4];
__device__ int      g_rowptr[NMAX + 1];
__device__ int      g_cursor[NMAX];
__device__ int      g_srcs[EMAX];
__device__ unsigned long long g_bpack[MAXSB];

// ---------------- threefry2x32 (exact JAX, partitionable mode) -------------
__host__ __device__ __forceinline__ unsigned rotl32(unsigned x, int r) {
    return (x << r) | (x >> (32 - r));
}

__host__ __device__ __forceinline__ void threefry2x32(
    unsigned k0, unsigned k1, unsigned x0, unsigned x1,
    unsigned& o0, unsigned& o1)
{
    unsigned ks0 = k0, ks1 = k1, ks2 = k0 ^ k1 ^ 0x1BD11BDAu;
    x0 += ks0; x1 += ks1;
#define TFR(r) { x0 += x1; x1 = rotl32(x1, r); x1 ^= x0; }
    TFR(13) TFR(15) TFR(26) TFR(6)   x0 += ks1; x1 += ks2 + 1u;
    TFR(17) TFR(29) TFR(16) TFR(24)  x0 += ks2; x1 += ks0 + 2u;
    TFR(13) TFR(15) TFR(26) TFR(6)   x0 += ks0; x1 += ks1 + 3u;
    TFR(17) TFR(29) TFR(16) TFR(24)  x0 += ks1; x1 += ks2 + 4u;
    TFR(13) TFR(15) TFR(26) TFR(6)   x0 += ks2; x1 += ks0 + 5u;
#undef TFR
    o0 = x0; o1 = x1;
}

// ---------------- bf16 split helpers ----------------------------------------
__device__ __forceinline__ void bsplit(float x, __nv_bfloat16& h, __nv_bfloat16& l) {
    h = __float2bfloat16(x);
    l = __float2bfloat16(x - __bfloat162float(h));
}

__device__ __forceinline__ unsigned packbf(__nv_bfloat16 lo16, __nv_bfloat16 hi16) {
    unsigned a = *(unsigned short*)&lo16;
    unsigned b = *(unsigned short*)&hi16;
    return a | (b << 16);
}

// ---------------- mma.sync bf16 m16n8k16 ------------------------------------
#define MMA_BF16(d, a0, a1, a2, a3, b0, b1)                                   \
    asm volatile("mma.sync.aligned.m16n8k16.row.col.f32.bf16.bf16.f32 "       \
        "{%0,%1,%2,%3}, {%4,%5,%6,%7}, {%8,%9}, {%0,%1,%2,%3};"               \
        : "+f"((d)[0]), "+f"((d)[1]), "+f"((d)[2]), "+f"((d)[3])              \
        : "r"(a0), "r"(a1), "r"(a2), "r"(a3), "r"(b0), "r"(b1))

// GEMM with fragment reuse; A tile rows addressed wr*32 + mt*16 (+8).
template<int NT, int BSTR, int NKS>
__device__ __forceinline__ void gemm_frag(
    const unsigned* __restrict__ Ah, const unsigned* __restrict__ Al,
    const unsigned* __restrict__ Bh, const unsigned* __restrict__ Bl,
    float acc[2][NT][4], int wr, int wn, int g, int t, int akw0)
{
#pragma unroll 1
    for (int ks = 0; ks < NKS; ks++) {
        const int kw = ks * 8;
        unsigned ah[2][4], al[2][4];
#pragma unroll
        for (int mt = 0; mt < 2; mt++) {
            const int r0 = (wr * 32 + mt * 16 + g) * STRIDE + akw0 + kw + t;
            const int r1 = r0 + 8 * STRIDE;
            ah[mt][0] = Ah[r0];     ah[mt][1] = Ah[r1];
            ah[mt][2] = Ah[r0 + 4]; ah[mt][3] = Ah[r1 + 4];
            al[mt][0] = Al[r0];     al[mt][1] = Al[r1];
            al[mt][2] = Al[r0 + 4]; al[mt][3] = Al[r1 + 4];
        }
#pragma unroll
        for (int nt = 0; nt < NT; nt++) {
            const int nb = (wn * (NT * 8) + nt * 8 + g) * BSTR + kw + t;
            const unsigned bh0 = Bh[nb], bh1 = Bh[nb + 4];
            const unsigned bl0 = Bl[nb], bl1 = Bl[nb + 4];
            MMA_BF16(acc[0][nt], ah[0][0], ah[0][1], ah[0][2], ah[0][3], bh0, bh1);
            MMA_BF16(acc[1][nt], ah[1][0], ah[1][1], ah[1][2], ah[1][3], bh0, bh1);
            MMA_BF16(acc[0][nt], ah[0][0], ah[0][1], ah[0][2], ah[0][3], bl0, bl1);
            MMA_BF16(acc[1][nt], ah[1][0], ah[1][1], ah[1][2], ah[1][3], bl0, bl1);
            MMA_BF16(acc[0][nt], al[0][0], al[0][1], al[0][2], al[0][3], bh0, bh1);
            MMA_BF16(acc[1][nt], al[1][0], al[1][1], al[1][2], al[1][3], bh0, bh1);
        }
    }
}

// ---------------- prep: W splits + flag reset + cursor zero ------------------
__global__ __launch_bounds__(256) void k_prep(
    const float* __restrict__ Ws1, const float* __restrict__ Ws2,
    const float* __restrict__ Wlin, int n)
{
    int idx = blockIdx.x * blockDim.x + threadIdx.x;
    if (idx < WSPLIT) {
        int w  = idx & 31;
        int nn = (idx >> 5) & 127;
        int c  = (idx >> 12) & 1;
        int m  = (idx >> 13) & 1;
        int l  = idx >> 14;
        const float* W = (m == 0 ? Ws1 : Ws2) + (size_t)l * DIM * DIM;
        int k0 = c * 64 + 2 * w;
        float w0 = W[(size_t)k0 * DIM + nn];
        float w1 = W[(size_t)(k0 + 1) * DIM + nn];
        __nv_bfloat16 h0, l0, h1, l1;
        bsplit(w0, h0, l0); bsplit(w1, h1, l1);
        g_wsph[idx] = packbf(h0, h1);
        g_wspl[idx] = packbf(l0, l1);
    } else if (idx < WSPLIT + WLINW) {
        int i = idx - WSPLIT;
        int nn = i >> 6;
        int w  = i & 63;
        int k0 = 2 * w;
        float w0 = Wlin[(size_t)k0 * ODIM + nn];
        float w1 = Wlin[(size_t)(k0 + 1) * ODIM + nn];
        __nv_bfloat16 h0, l0, h1, l1;
        bsplit(w0, h0, l0); bsplit(w1, h1, l1);
        g_wlh[nn * 64 + w] = packbf(h0, h1);
        g_wll[nn * 64 + w] = packbf(l0, l1);
    } else if (idx < WSPLIT + WLINW + MAXSB) {
        g_bpack[idx - WSPLIT - WLINW] = 0ULL;
    } else {
        int i = idx - WSPLIT - WLINW - MAXSB;
        if (i < n) g_cursor[i] = 0;
    }
}

// ---------------- CSR build (8 edges/thread via 2x int4) ---------------------
__global__ __launch_bounds__(256) void k_hist(const int* __restrict__ ei, int e, int n) {
    int i8 = (blockIdx.x * blockDim.x + threadIdx.x) * 8;
    if (i8 >= e) return;
    if ((e & 7) == 0) {
        int4 d0 = *(const int4*)(ei + e + i8);
        int4 d1 = *(const int4*)(ei + e + i8 + 4);
        if ((unsigned)d0.x < (unsigned)n) atomicAdd(&g_cursor[d0.x], 1);
        if ((unsigned)d0.y < (unsigned)n) atomicAdd(&g_cursor[d0.y], 1);
        if ((unsigned)d0.z < (unsigned)n) atomicAdd(&g_cursor[d0.z], 1);
        if ((unsigned)d0.w < (unsigned)n) atomicAdd(&g_cursor[d0.w], 1);
        if ((unsigned)d1.x < (unsigned)n) atomicAdd(&g_cursor[d1.x], 1);
        if ((unsigned)d1.y < (unsigned)n) atomicAdd(&g_cursor[d1.y], 1);
        if ((unsigned)d1.z < (unsigned)n) atomicAdd(&g_cursor[d1.z], 1);
        if ((unsigned)d1.w < (unsigned)n) atomicAdd(&g_cursor[d1.w], 1);
    } else {
        for (int q = 0; q < 8 && i8 + q < e; q++) {
            int dst = ei[e + i8 + q];
            if ((unsigned)dst < (unsigned)n) atomicAdd(&g_cursor[dst], 1);
        }
    }
}

// fused scan: per-block scan + decoupled lookback + rowptr/cursor writes
__global__ __launch_bounds__(1024) void k_scan(int n, int nblk) {
    __shared__ int wsum[32];
    __shared__ int soff;
    const int t = threadIdx.x, lane = t & 31, w = t >> 5;
    const int base = blockIdx.x * SCANB + t * 4;
    int v0 = 0, v1 = 0, v2 = 0, v3 = 0;
    if (base + 0 < n) v0 = g_cursor[base + 0];
    if (base + 1 < n) v1 = g_cursor[base + 1];
    if (base + 2 < n) v2 = g_cursor[base + 2];
    if (base + 3 < n) v3 = g_cursor[base + 3];
    int s = v0 + v1 + v2 + v3;
    int x = s;
#pragma unroll
    for (int off = 1; off < 32; off <<= 1) {
        int y = __shfl_up_sync(0xffffffffu, x, off);
        if (lane >= off) x += y;
    }
    if (lane == 31) wsum[w] = x;
    __syncthreads();
    if (w == 0) {
        int y = wsum[lane];
#pragma unroll
        for (int off = 1; off < 32; off <<= 1) {
            int z2 = __shfl_up_sync(0xffffffffu, y, off);
            if (lane >= off) y += z2;
        }
        wsum[lane] = y;
    }
    __syncthreads();
    const int total = wsum[31];
    if (t == 0) {
        atomicExch(&g_bpack[blockIdx.x],
                   (1ULL << 63) | (unsigned long long)(unsigned)total);
        int run = 0;
        for (int b = 0; b < blockIdx.x; b++) {
            unsigned long long v;
            do { v = atomicAdd(&g_bpack[b], 0ULL); } while (!(v >> 63));
            run += (int)(unsigned)(v & 0xffffffffULL);
        }
        soff = run;
        if (blockIdx.x == nblk - 1) g_rowptr[n] = run + total;
    }
    __syncthreads();
    const int excl = (x - s) + (w ? wsum[w - 1] : 0) + soff;
    if (base + 0 < n) { int v = excl;                 g_rowptr[base + 0] = v; g_cursor[base + 0] = v; }
    if (base + 1 < n) { int v = excl + v0;            g_rowptr[base + 1] = v; g_cursor[base + 1] = v; }
    if (base + 2 < n) { int v = excl + v0 + v1;       g_rowptr[base + 2] = v; g_cursor[base + 2] = v; }
    if (base + 3 < n) { int v = excl + v0 + v1 + v2;  g_rowptr[base + 3] = v; g_cursor[base + 3] = v; }
}

__global__ __launch_bounds__(256) void k_scatter(const int* __restrict__ ei, int e, int n) {
    int i8 = (blockIdx.x * blockDim.x + threadIdx.x) * 8;
    if (i8 >= e) return;
    if ((e & 7) == 0) {
        int4 s0 = *(const int4*)(ei + i8);
        int4 s1 = *(const int4*)(ei + i8 + 4);
        int4 d0 = *(const int4*)(ei + e + i8);
        int4 d1 = *(const int4*)(ei + e + i8 + 4);
        int ss[8] = { s0.x, s0.y, s0.z, s0.w, s1.x, s1.y, s1.z, s1.w };
        int dd[8] = { d0.x, d0.y, d0.z, d0.w, d1.x, d1.y, d1.z, d1.w };
#pragma unroll
        for (int q = 0; q < 8; q++) {
            if ((unsigned)dd[q] < (unsigned)n && (unsigned)ss[q] < (unsigned)n) {
                int pos = atomicAdd(&g_cursor[dd[q]], 1);
                if ((unsigned)pos < (unsigned)EMAX) g_srcs[pos] = ss[q];
            }
        }
    } else {
        for (int q = 0; q < 8 && i8 + q < e; q++) {
            int dst = ei[e + i8 + q];
            int src = ei[i8 + q];
            if ((unsigned)dst < (unsigned)n && (unsigned)src < (unsigned)n) {
                int pos = atomicAdd(&g_cursor[dst], 1);
                if ((unsigned)pos < (unsigned)EMAX) g_srcs[pos] = src;
            }
        }
    }
}

// ---------- aggregation + split + dropout mask gen (warp per node) ----------
__global__ __launch_bounds__(256) void k_aggregate(
    const float* __restrict__ xin, int use_x, int n,
    unsigned dk0, unsigned dk1)
{
    const int gw = (blockIdx.x * 256 + threadIdx.x) >> 5;
    if (gw >= n) return;
    const int lane = threadIdx.x & 31;

    const unsigned base_j = (unsigned)gw * 128u + (unsigned)lane;
#pragma unroll
    for (int w = 0; w < 4; w++) {
        unsigned a, b;
        threefry2x32(dk0, dk1, 0u, base_j + (unsigned)(w * 32), a, b);
        unsigned bits = a ^ b;
        float u = __uint_as_float((bits >> 9) | 0x3f800000u) - 1.0f;
        unsigned word = __ballot_sync(0xffffffffu, u < 0.9f);
        if (lane == w) g_mask[gw * 4 + w] = word;
    }

    const float4* b4 = (const float4*)(use_x ? xin : g_h);
    float4 acc = b4[(size_t)gw * 32 + lane];
    int p = g_rowptr[gw];
    const int pe = g_rowptr[gw + 1];
    for (; p + 4 <= pe; p += 4) {
        int s0 = g_srcs[p], s1 = g_srcs[p + 1], s2 = g_srcs[p + 2], s3 = g_srcs[p + 3];
        float4 v0 = b4[(size_t)s0 * 32 + lane];
        float4 v1 = b4[(size_t)s1 * 32 + lane];
        float4 v2 = b4[(size_t)s2 * 32 + lane];
        float4 v3 = b4[(size_t)s3 * 32 + lane];
        acc.x += v0.x; acc.y += v0.y; acc.z += v0.z; acc.w += v0.w;
        acc.x += v1.x; acc.y += v1.y; acc.z += v1.z; acc.w += v1.w;
        acc.x += v2.x; acc.y += v2.y; acc.z += v2.z; acc.w += v2.w;
        acc.x += v3.x; acc.y += v3.y; acc.z += v3.z; acc.w += v3.w;
    }
    for (; p < pe; ++p) {
        float4 v = b4[(size_t)g_srcs[p] * 32 + lane];
        acc.x += v.x; acc.y += v.y; acc.z += v.z; acc.w += v.w;
    }
    __nv_bfloat16 h0, l0, h1, l1, h2, l2, h3, l3;
    bsplit(acc.x, h0, l0); bsplit(acc.y, h1, l1);
    bsplit(acc.z, h2, l2); bsplit(acc.w, h3, l3);
    const size_t o = (size_t)gw * 64 + lane * 2;
    g_ah[o]     = packbf(h0, h1);
    g_ah[o + 1] = packbf(h2, h3);
    g_al[o]     = packbf(l0, l1);
    g_al[o + 1] = packbf(l2, l3);
}

// ---------------- fused MLP, 64-row tiles -------------------------------------
#define BUFW     (TM * STRIDE)                 // 4352 words
#define WBUF     (128 * WSTR)                  // 4608 words
#define SMEM_MMA (2048 + 2 * BUFW * 4 + 2 * WBUF * 4)   // 73,728 B

template<bool DO_LIN>
__global__ __launch_bounds__(256, 3) void k_mlp_mma(
    const float* __restrict__ b1g, const float* __restrict__ b2g,
    const float* __restrict__ blin, float* __restrict__ outp,
    int lidx, int nrows)
{
    extern __shared__ char smem[];
    float*    sB1 = (float*)smem;
    float*    sB2 = (float*)(smem + 512);
    float*    sBo = (float*)(smem + 1024);
    unsigned* sAh = (unsigned*)(smem + 2048);
    unsigned* sAl = sAh + BUFW;
    unsigned* sWh = sAl + BUFW;
    unsigned* sWl = sWh + WBUF;

    const int tid = threadIdx.x;
    const int wid = tid >> 5;
    const int lane = tid & 31;
    const int wr = wid & 1;
    const int wn = wid >> 1;
    const int g = lane >> 2;
    const int t = lane & 3;

    const int row0 = blockIdx.x * TM;
    const int avail = (nrows - row0 < TM) ? (nrows - row0) : TM;

    if (tid < 128) { sB1[tid] = b1g[tid]; sB2[tid] = b2g[tid]; }
    if (DO_LIN && tid < 64) sBo[tid] = blin[tid];

    for (int i = tid; i < 1024; i += 256) {
        int r  = i >> 4;
        int w4 = (i & 15) * 4;
        uint4 vh = make_uint4(0, 0, 0, 0), vl = make_uint4(0, 0, 0, 0);
        if (r < avail) {
            vh = *(const uint4*)(g_ah + (size_t)(row0 + r) * 64 + w4);
            vl = *(const uint4*)(g_al + (size_t)(row0 + r) * 64 + w4);
        }
        *(uint4*)(sAh + r * STRIDE + w4) = vh;
        *(uint4*)(sAl + r * STRIDE + w4) = vl;
    }

    float acc[2][4][4];
#pragma unroll
    for (int mt = 0; mt < 2; mt++)
#pragma unroll
        for (int nt = 0; nt < 4; nt++)
#pragma unroll
            for (int q = 0; q < 4; q++) acc[mt][nt][q] = 0.f;

#pragma unroll 1
    for (int c = 0; c < 2; c++) {
        const unsigned* gh = g_wsph + ((lidx * 2 + 0) * 2 + c) * 4096;
        const unsigned* gl = g_wspl + ((lidx * 2 + 0) * 2 + c) * 4096;
        for (int i = tid; i < 1024; i += 256) {
            int nn = i >> 3;
            int w4 = (i & 7) * 4;
            *(uint4*)(sWh + nn * WSTR + w4) = *(const uint4*)(gh + nn * 32 + w4);
            *(uint4*)(sWl + nn * WSTR + w4) = *(const uint4*)(gl + nn * 32 + w4);
        }
        __syncthreads();
        gemm_frag<4, WSTR, 4>(sAh, sAl, sWh, sWl, acc, wr, wn, g, t, c * 32);
        __syncthreads();
    }

    // epilogue1: t = relu(D1 + b1) -> split back into sAh/sAl
#pragma unroll
    for (int mt = 0; mt < 2; mt++) {
        const int r0 = wr * 32 + mt * 16 + g;
#pragma unroll
        for (int nt = 0; nt < 4; nt++) {
            const int c0 = wn * 32 + nt * 8 + 2 * t;
            const float bv0 = sB1[c0], bv1 = sB1[c0 + 1];
            float v00 = fmaxf(acc[mt][nt][0] + bv0, 0.f);
            float v01 = fmaxf(acc[mt][nt][1] + bv1, 0.f);
            float v10 = fmaxf(acc[mt][nt][2] + bv0, 0.f);
            float v11 = fmaxf(acc[mt][nt][3] + bv1, 0.f);
            __nv_bfloat16 h00, l00, h01, l01, h10, l10, h11, l11;
            bsplit(v00, h00, l00); bsplit(v01, h01, l01);
            bsplit(v10, h10, l10); bsplit(v11, h11, l11);
            const int w0 = r0 * STRIDE + (c0 >> 1);
            const int w1 = w0 + 8 * STRIDE;
            sAh[w0] = packbf(h00, h01);  sAl[w0] = packbf(l00, l01);
            sAh[w1] = packbf(h10, h11);  sAl[w1] = packbf(l10, l11);
            acc[mt][nt][0] = 0.f; acc[mt][nt][1] = 0.f;
            acc[mt][nt][2] = 0.f; acc[mt][nt][3] = 0.f;
        }
    }
    __syncthreads();

#pragma unroll 1
    for (int c = 0; c < 2; c++) {
        const unsigned* gh = g_wsph + ((lidx * 2 + 1) * 2 + c) * 4096;
        const unsigned* gl = g_wspl + ((lidx * 2 + 1) * 2 + c) * 4096;
        for (int i = tid; i < 1024; i += 256) {
            int nn = i >> 3;
            int w4 = (i & 7) * 4;
            *(uint4*)(sWh + nn * WSTR + w4) = *(const uint4*)(gh + nn * 32 + w4);
            *(uint4*)(sWl + nn * WSTR + w4) = *(const uint4*)(gl + nn * 32 + w4);
        }
        __syncthreads();
        gemm_frag<4, WSTR, 4>(sAh, sAl, sWh, sWl, acc, wr, wn, g, t, c * 32);
        __syncthreads();
    }

    // precomputed dropout mask (one word per (row, wn))
    unsigned mw[2][2];
#pragma unroll
    for (int mt = 0; mt < 2; mt++)
#pragma unroll
        for (int rr = 0; rr < 2; rr++) {
            int grow = row0 + wr * 32 + mt * 16 + g + rr * 8;
            mw[mt][rr] = (grow < nrows) ? g_mask[grow * 4 + wn] : 0u;
        }
    const float INV = 1.0f / 0.9f;

    // epilogue2: h = dropout(relu(D2 + b2))
#pragma unroll
    for (int mt = 0; mt < 2; mt++) {
        const int r0 = wr * 32 + mt * 16 + g;
        const int grow0 = row0 + r0;
        const int grow1 = grow0 + 8;
#pragma unroll
        for (int nt = 0; nt < 4; nt++) {
            const int c0 = wn * 32 + nt * 8 + 2 * t;
            const float bv0 = sB2[c0], bv1 = sB2[c0 + 1];
            const int b0 = nt * 8 + 2 * t;
            {
                float m0 = ((mw[mt][0] >> b0) & 1u) ? INV : 0.f;
                float m1 = ((mw[mt][0] >> (b0 + 1)) & 1u) ? INV : 0.f;
                float v0 = fmaxf(acc[mt][nt][0] + bv0, 0.f) * m0;
                float v1 = fmaxf(acc[mt][nt][1] + bv1, 0.f) * m1;
                if (DO_LIN) {
                    __nv_bfloat16 h0, l0, h1, l1;
                    bsplit(v0, h0, l0); bsplit(v1, h1, l1);
                    const int w0 = r0 * STRIDE + (c0 >> 1);
                    sAh[w0] = packbf(h0, h1);  sAl[w0] = packbf(l0, l1);
                } else if (grow0 < nrows) {
                    *(float2*)(g_h + (size_t)grow0 * DIM + c0) = make_float2(v0, v1);
                }
            }
            {
                float m0 = ((mw[mt][1] >> b0) & 1u) ? INV : 0.f;
                float m1 = ((mw[mt][1] >> (b0 + 1)) & 1u) ? INV : 0.f;
                float v0 = fmaxf(acc[mt][nt][2] + bv0, 0.f) * m0;
                float v1 = fmaxf(acc[mt][nt][3] + bv1, 0.f) * m1;
                if (DO_LIN) {
                    __nv_bfloat16 h0, l0, h1, l1;
                    bsplit(v0, h0, l0); bsplit(v1, h1, l1);
                    const int w1 = (r0 + 8) * STRIDE + (c0 >> 1);
                    sAh[w1] = packbf(h0, h1);  sAl[w1] = packbf(l0, l1);
                } else if (grow1 < nrows) {
                    *(float2*)(g_h + (size_t)grow1 * DIM + c0) = make_float2(v0, v1);
                }
            }
        }
    }

    if (DO_LIN) {
        __syncthreads();
        // stage Wlin split: 64 rows x 64 words (stride STRIDE; 4352 <= WBUF)
        for (int i = tid; i < 1024; i += 256) {
            int nn = i >> 4;
            int w4 = (i & 15) * 4;
            *(uint4*)(sWh + nn * STRIDE + w4) = *(const uint4*)(g_wlh + nn * 64 + w4);
            *(uint4*)(sWl + nn * STRIDE + w4) = *(const uint4*)(g_wll + nn * 64 + w4);
        }
        __syncthreads();

        float la[2][2][4];
#pragma unroll
        for (int mt = 0; mt < 2; mt++)
#pragma unroll
            for (int nt = 0; nt < 2; nt++)
#pragma unroll
                for (int q = 0; q < 4; q++) la[mt][nt][q] = 0.f;

        gemm_frag<2, STRIDE, 8>(sAh, sAl, sWh, sWl, la, wr, wn, g, t, 0);

#pragma unroll
        for (int mt = 0; mt < 2; mt++) {
            const int grow0 = row0 + wr * 32 + mt * 16 + g;
            const int grow1 = grow0 + 8;
#pragma unroll
            for (int nt = 0; nt < 2; nt++) {
                const int c0 = wn * 16 + nt * 8 + 2 * t;
                const float bv0 = sBo[c0], bv1 = sBo[c0 + 1];
                if (grow0 < nrows)
                    *(float2*)(outp + (size_t)grow0 * ODIM + c0) =
                        make_float2(la[mt][nt][0] + bv0, la[mt][nt][1] + bv1);
                if (grow1 < nrows)
                    *(float2*)(outp + (size_t)grow1 * ODIM + c0) =
                        make_float2(la[mt][nt][2] + bv0, la[mt][nt][3] + bv1);
            }
        }
    }
}

// ---------------- launch ----------------------------------------------------
extern "C" void kernel_launch(void* const* d_in, const int* in_sizes, int n_in,
                              void* d_out, int out_size)
{
    const float* x    = (const float*)d_in[0];
    const int*   ei   = (const int*)d_in[1];
    const float* Ws1  = (const float*)d_in[2];
    const float* bs1  = (const float*)d_in[3];
    const float* Ws2  = (const float*)d_in[4];
    const float* bs2  = (const float*)d_in[5];
    const float* Wlin = (const float*)d_in[6];
    const float* blin = (const float*)d_in[7];
    float*       out  = (float*)d_out;

    const int n = in_sizes[0] / DIM;
    const int e = in_sizes[1] / 2;
    if (n > NMAX || e > EMAX || n <= 0) return;

    cudaFuncSetAttribute(k_mlp_mma<false>, cudaFuncAttributeMaxDynamicSharedMemorySize, SMEM_MMA);
    cudaFuncSetAttribute(k_mlp_mma<true>,  cudaFuncAttributeMaxDynamicSharedMemorySize, SMEM_MMA);

    unsigned dk0[3], dk1[3];
    for (int l = 0; l < 3; l++)
        threefry2x32(0u, 42u, 0u, (unsigned)l, dk0[l], dk1[l]);

    const int nsb = (n + SCANB - 1) / SCANB;
    const int e8  = (e + 7) / 8;

    k_prep   <<<(WSPLIT + WLINW + MAXSB + n + 255) / 256, 256>>>(Ws1, Ws2, Wlin, n);
    k_hist   <<<(e8 + 255) / 256, 256>>>(ei, e, n);
    k_scan   <<<nsb, 1024>>>(n, nsb);
    k_scatter<<<(e8 + 255) / 256, 256>>>(ei, e, n);

    const int gblk = (n + TM - 1) / TM;
    const int ablk = (n * 32 + 255) / 256;
    for (int l = 0; l < 3; l++) {
        k_aggregate<<<ablk, 256>>>(x, l == 0 ? 1 : 0, n, dk0[l], dk1[l]);
        if (l < 2)
            k_mlp_mma<false><<<gblk, 256, SMEM_MMA>>>(
                bs1 + (size_t)l * DIM, bs2 + (size_t)l * DIM,
                blin, out, l, n);
        else
            k_mlp_mma<true><<<gblk, 256, SMEM_MMA>>>(
                bs1 + (size_t)l * DIM, bs2 + (size_t)l * DIM,
                blin, out, l, n);
    }
}